// round 17
// baseline (speedup 1.0000x reference)
#include <cuda_runtime.h>
#include <cuda_bf16.h>
#include <cstdint>

#define BN    2048
#define DD    32
#define NIDS  8192
#define KNN   30
#define NTHR  256
#define MT    64                // rows per den tile
#define NT    64                // cols per den tile
#define NB    (BN / 64)         // 32 blocks per dim
#define NDEN  (NB * (NB + 1) / 2)   // 528 triangular tiles (y >= x)
#define NSP   128               // sparse CTAs (warp per 2 rows)
#define NCTAS_ALL (NDEN + NSP)  // 656
#define BCAP  32
#define RS    144               // smem row stride: 128B (hi|lo) + 16B pad

// Scratch (no allocations allowed)
__device__ float g_sq[BN];
__device__ __align__(16) unsigned g_zhl[BN * 32];  // 128B/row: 16 u32 hi | 16 u32 lo
__device__ float g_den[BN];      // atomic fp32 accumulation (zeroed by prep)
__device__ float g_num[BN];
__device__ float g_any[BN];
__device__ int   g_bkt[NIDS * BCAP];
__device__ int   g_bcnt[NIDS];
__device__ unsigned g_cnt = 0;

__device__ __forceinline__ float fsqrt_approx(float x) {
    float r; asm("sqrt.approx.f32 %0, %1;" : "=f"(r) : "f"(x)); return r;
}
__device__ __forceinline__ float pair_e(float dot, float sqsum) {
    float d2 = fmaf(-2.f, dot, sqsum);
    d2 = fmaxf(d2, 1e-20f);
    return __expf(-fsqrt_approx(d2));
}
__device__ __forceinline__ uint32_t bpack(__nv_bfloat16 a, __nv_bfloat16 b) {
    __nv_bfloat162 p; p.x = a; p.y = b;
    return *reinterpret_cast<uint32_t*>(&p);
}
__device__ __forceinline__ uint32_t smem_u32(const void* p) {
    uint32_t a;
    asm("{ .reg .u64 t; cvta.to.shared.u64 t, %1; cvt.u32.u64 %0, t; }" : "=r"(a) : "l"(p));
    return a;
}
__device__ __forceinline__ void mma_bf16(float* d, const uint32_t* a,
                                         const uint32_t* b, const float* c) {
    asm volatile(
        "mma.sync.aligned.m16n8k16.row.col.f32.bf16.bf16.f32 "
        "{%0,%1,%2,%3}, {%4,%5,%6,%7}, {%8,%9}, {%10,%11,%12,%13};"
        : "=f"(d[0]), "=f"(d[1]), "=f"(d[2]), "=f"(d[3])
        : "r"(a[0]), "r"(a[1]), "r"(a[2]), "r"(a[3]),
          "r"(b[0]), "r"(b[1]),
          "f"(c[0]), "f"(c[1]), "f"(c[2]), "f"(c[3]));
}
#define LDSM_X4(d, addr) \
    asm volatile("ldmatrix.sync.aligned.m8n8.x4.shared.b16 {%0,%1,%2,%3}, [%4];" \
        : "=r"((d)[0]), "=r"((d)[1]), "=r"((d)[2]), "=r"((d)[3]) : "r"(addr))

// Kernel 1: grid 72. bid<64: hi/lo split + norms. bid>=64: bucket fill + g_den zero.
__global__ void __launch_bounds__(NTHR)
prep_kernel(const float* __restrict__ z, const int* __restrict__ sid) {
    const int t = threadIdx.x;
    if (blockIdx.x < 64) {
        const int gid = blockIdx.x * NTHR + t;
        const int r = gid >> 3, c = gid & 7;
        float4 v = ((const float4*)z)[r * 8 + c];
        float s = v.x * v.x + v.y * v.y + v.z * v.z + v.w * v.w;
        s += __shfl_xor_sync(0xffffffffu, s, 1);
        s += __shfl_xor_sync(0xffffffffu, s, 2);
        s += __shfl_xor_sync(0xffffffffu, s, 4);
        if (c == 0) g_sq[r] = s;

        __nv_bfloat16 hx = __float2bfloat16(v.x), hy = __float2bfloat16(v.y);
        __nv_bfloat16 hz = __float2bfloat16(v.z), hw = __float2bfloat16(v.w);
        __nv_bfloat16 lx = __float2bfloat16(v.x - __bfloat162float(hx));
        __nv_bfloat16 ly = __float2bfloat16(v.y - __bfloat162float(hy));
        __nv_bfloat16 lz = __float2bfloat16(v.z - __bfloat162float(hz));
        __nv_bfloat16 lw = __float2bfloat16(v.w - __bfloat162float(hw));
        g_zhl[r * 32 + c * 2]          = bpack(hx, hy);
        g_zhl[r * 32 + c * 2 + 1]      = bpack(hz, hw);
        g_zhl[r * 32 + 16 + c * 2]     = bpack(lx, ly);
        g_zhl[r * 32 + 16 + c * 2 + 1] = bpack(lz, lw);
    } else {
        const int j = (blockIdx.x - 64) * NTHR + t;   // 8 CTAs cover 2048 j's
        g_den[j] = 0.f;                               // zero accumulator each replay
        const int id = sid[j];
        int slot = atomicAdd(&g_bcnt[id], 1);
        if (slot < BCAP) g_bkt[id * BCAP + slot] = j;
    }
}

// Kernel 2: grid 656 (1D).
//  u<528 : symmetric den tile (x,y), y>=x over 64x64 blocks; pairs masked j>i;
//          each e credited to den[i] (row) AND den[j] (col).
//  u>=528: sparse num/valid (warp per 2 rows).
// Last of 656 CTAs: final scalar reduction + scratch reset.
__global__ void __launch_bounds__(NTHR, 4)
main_kernel(const float* __restrict__ z,
            const int* __restrict__ knn,
            const int* __restrict__ sid,
            float* __restrict__ out) {
    __shared__ __align__(16) char s_a[MT * RS];
    __shared__ __align__(16) char s_b[NT * RS];
    __shared__ float s_pr[MT][4];    // row partials per wn
    __shared__ float s_pc[NT][2];    // col partials per wm
    __shared__ float s_sqi[MT];
    __shared__ float s_sqj[NT];
    __shared__ bool s_last;

    const int t = threadIdx.x;
    const int w = t >> 5, lane = t & 31;
    const int gID = lane >> 2, tig = lane & 3;
    const int u = blockIdx.x;

    if (u < NDEN) {
        // decode triangular (x, y), y >= x
        int x = 0, cum = 0;
        while (u >= cum + (NB - x)) { cum += NB - x; x++; }
        const int y = x + (u - cum);

        // ---- load tiles: A = rows [x*64,+64), B = rows [y*64,+64) ----
        const uint4* src = (const uint4*)g_zhl;
#pragma unroll
        for (int i = t; i < (MT + NT) * 8; i += NTHR) {
            int row = i >> 3, uu = i & 7;
            if (i < MT * 8)
                *(uint4*)(s_a + row * RS + uu * 16) = src[(x * MT + row) * 8 + uu];
            else {
                int r2 = row - MT;
                *(uint4*)(s_b + r2 * RS + uu * 16) = src[(y * NT + r2) * 8 + uu];
            }
        }
        if (t < MT) s_sqi[t] = g_sq[x * MT + t];
        else if (t < MT + NT) s_sqj[t - MT] = g_sq[y * NT + (t - MT)];
        if (t < NT) { s_pc[t][0] = 0.f; s_pc[t][1] = 0.f; }
        __syncthreads();

        // ---- warp tile 32x16: wm in 0..1 (32 rows), wn in 0..3 (16 cols) ----
        const int wm = w & 1, wn = w >> 1;
        float acc[2][2][4];
#pragma unroll
        for (int mi = 0; mi < 2; mi++)
#pragma unroll
            for (int ni = 0; ni < 2; ni++)
#pragma unroll
                for (int q = 0; q < 4; q++) acc[mi][ni][q] = 0.f;

        uint32_t aBase[2], bBase;
        {
            const uint32_t sa32 = smem_u32(s_a), sb32 = smem_u32(s_b);
            const int m = lane >> 3, r = lane & 7;
#pragma unroll
            for (int mi = 0; mi < 2; mi++)
                aBase[mi] = sa32 + (uint32_t)((wm * 32 + mi * 16 + (m & 1) * 8 + r) * RS
                                              + (m >> 1) * 16);
            bBase = sb32 + (uint32_t)((wn * 16 + (m >> 1) * 8 + r) * RS + (m & 1) * 16);
        }

        // combos: 0 = hi*hi, 1 = hi*lo, 2 = lo*hi  (lo at +64B)
#pragma unroll
        for (int combo = 0; combo < 3; combo++) {
            const uint32_t aoff = (combo == 2) ? 64u : 0u;
            const uint32_t boff = (combo == 1) ? 64u : 0u;
#pragma unroll
            for (int kk = 0; kk < 2; kk++) {
                const uint32_t ko = (uint32_t)(kk * 32);
                uint32_t af[2][4], bf[4];
                LDSM_X4(af[0], aBase[0] + aoff + ko);
                LDSM_X4(af[1], aBase[1] + aoff + ko);
                LDSM_X4(bf, bBase + boff + ko);   // {ni0_k0, ni0_k8, ni1_k0, ni1_k8}
#pragma unroll
                for (int mi = 0; mi < 2; mi++) {
                    mma_bf16(acc[mi][0], af[mi], &bf[0], acc[mi][0]);
                    mma_bf16(acc[mi][1], af[mi], &bf[2], acc[mi][1]);
                }
            }
        }

        // ---- epilogue: mask j>i, row sums AND col sums ----
        float cs0[2] = {0.f, 0.f};
        float cs1[2] = {0.f, 0.f};
#pragma unroll
        for (int mi = 0; mi < 2; mi++) {
            const int lr0 = wm * 32 + mi * 16 + gID;
            const int lr1 = lr0 + 8;
            const int gi0 = x * MT + lr0, gi1 = x * MT + lr1;
            const float sq0 = s_sqi[lr0], sq1 = s_sqi[lr1];
            float rs0 = 0.f, rs1 = 0.f;
#pragma unroll
            for (int ni = 0; ni < 2; ni++) {
                const int cl = wn * 16 + ni * 8 + tig * 2;
                const int gj0 = y * NT + cl, gj1 = gj0 + 1;
                const float sa = s_sqj[cl], sb = s_sqj[cl + 1];
                float e00 = pair_e(acc[mi][ni][0], sq0 + sa); e00 = (gj0 > gi0) ? e00 : 0.f;
                float e01 = pair_e(acc[mi][ni][1], sq0 + sb); e01 = (gj1 > gi0) ? e01 : 0.f;
                float e10 = pair_e(acc[mi][ni][2], sq1 + sa); e10 = (gj0 > gi1) ? e10 : 0.f;
                float e11 = pair_e(acc[mi][ni][3], sq1 + sb); e11 = (gj1 > gi1) ? e11 : 0.f;
                rs0 += e00 + e01;
                rs1 += e10 + e11;
                cs0[ni] += e00 + e10;
                cs1[ni] += e01 + e11;
            }
            rs0 += __shfl_xor_sync(0xffffffffu, rs0, 1);
            rs0 += __shfl_xor_sync(0xffffffffu, rs0, 2);
            rs1 += __shfl_xor_sync(0xffffffffu, rs1, 1);
            rs1 += __shfl_xor_sync(0xffffffffu, rs1, 2);
            if (tig == 0) { s_pr[lr0][wn] = rs0; s_pr[lr1][wn] = rs1; }
        }
        // column reduce over gID (lanes differing in bits 2..4)
#pragma unroll
        for (int ni = 0; ni < 2; ni++) {
#pragma unroll
            for (int off = 4; off <= 16; off <<= 1) {
                cs0[ni] += __shfl_xor_sync(0xffffffffu, cs0[ni], off);
                cs1[ni] += __shfl_xor_sync(0xffffffffu, cs1[ni], off);
            }
        }
        if (gID == 0) {
#pragma unroll
            for (int ni = 0; ni < 2; ni++) {
                const int cl = wn * 16 + ni * 8 + tig * 2;
                atomicAdd(&s_pc[cl][wm], cs0[ni]);
                atomicAdd(&s_pc[cl + 1][wm], cs1[ni]);
            }
        }
        __syncthreads();
        if (t < MT)
            atomicAdd(&g_den[x * MT + t],
                      (s_pr[t][0] + s_pr[t][1]) + (s_pr[t][2] + s_pr[t][3]));
        else if (t < MT + NT) {
            int c = t - MT;
            atomicAdd(&g_den[y * NT + c], s_pc[c][0] + s_pc[c][1]);
        }
    } else {
        // ---- sparse num / valid: warp handles 2 rows (128 sparse CTAs) ----
        const int s = u - NDEN;            // 0..127
#pragma unroll
        for (int rr = 0; rr < 2; rr++) {
            const int i = s * 16 + w * 2 + rr;
            const int sidi = sid[i];
            int id = (lane < KNN) ? knn[sidi * KNN + lane] : (-1 - lane);
            unsigned mm = __match_any_sync(0xffffffffu, id);
            bool dup = (mm & ((1u << lane) - 1u)) != 0u;
            float num = 0.f;
            bool found = false;
            if (lane < KNN && !dup) {
                int cnt = g_bcnt[id];
                if (cnt > BCAP) cnt = BCAP;
                if (cnt > 0) {
                    int jarr[BCAP];
                    for (int s2 = 0; s2 < cnt; s2++) jarr[s2] = g_bkt[id * BCAP + s2];
                    for (int a = 1; a < cnt; a++) {
                        int v = jarr[a]; int b = a - 1;
                        while (b >= 0 && jarr[b] > v) { jarr[b + 1] = jarr[b]; b--; }
                        jarr[b + 1] = v;
                    }
                    for (int s2 = 0; s2 < cnt; s2++) {
                        int jj = jarr[s2];
                        if (jj != i) {
                            const float* zi = z + i * DD;
                            const float* zj = z + jj * DD;
                            float dot = 0.f;
#pragma unroll
                            for (int k = 0; k < DD; k++) dot = fmaf(zi[k], zj[k], dot);
                            num += pair_e(dot, g_sq[i] + g_sq[jj]);
                            found = true;
                        }
                    }
                }
            }
#pragma unroll
            for (int off = 16; off > 0; off >>= 1)
                num += __shfl_xor_sync(0xffffffffu, num, off);
            unsigned bal = __ballot_sync(0xffffffffu, found);
            if (lane == 0) {
                g_num[i] = num;
                g_any[i] = bal ? 1.f : 0.f;
            }
        }
    }

    // ---- last-block final reduction ----
    __threadfence();
    if (t == 0) {
        unsigned old = atomicAdd(&g_cnt, 1u);
        s_last = (old == NCTAS_ALL - 1);
    }
    __syncthreads();
    if (!s_last) return;

    __threadfence();
    float tot = 0.f, cnt = 0.f;
    for (int i = t; i < BN; i += NTHR) {
        float dv = __ldcg(&g_den[i]);
        float nv = __ldcg(&g_num[i]);
        bool valid = __ldcg(&g_any[i]) > 0.f;
        float sr = nv / dv;
        float loss = -__logf(sr + 1e-8f);
        tot += valid ? loss : 0.f;
        cnt += valid ? 1.f : 0.f;
    }
#pragma unroll
    for (int off = 16; off > 0; off >>= 1) {
        tot += __shfl_xor_sync(0xffffffffu, tot, off);
        cnt += __shfl_xor_sync(0xffffffffu, cnt, off);
    }
    if (lane == 0) { s_pr[w][0] = tot; s_pr[w][1] = cnt; }
    __syncthreads();
    if (t == 0) {
        float T = 0.f, C = 0.f;
#pragma unroll
        for (int ww = 0; ww < NTHR / 32; ww++) { T += s_pr[ww][0]; C += s_pr[ww][1]; }
        out[0] = (C > 0.f) ? (T / C) : 0.f;
        g_cnt = 0;
    }
    for (int i = t; i < NIDS; i += NTHR) g_bcnt[i] = 0;  // reset for next replay
}

extern "C" void kernel_launch(void* const* d_in, const int* in_sizes, int n_in,
                              void* d_out, int out_size) {
    const float* z   = (const float*)d_in[0];
    const int*   knn = (const int*)d_in[1];
    const int*   sid = (const int*)d_in[2];
    (void)in_sizes; (void)n_in; (void)out_size;

    prep_kernel<<<72, NTHR>>>(z, sid);
    main_kernel<<<NCTAS_ALL, NTHR>>>(z, knn, sid, (float*)d_out);
}